// round 15
// baseline (speedup 1.0000x reference)
#include <cuda_runtime.h>
#include <cuda_fp16.h>
#include <cstdint>

#define N_NODES 20000
#define N_EDGES 160000
#define E_TOT   180000     // edges + self loops
#define FEAT    512
#define HEADS   4
#define HC      2048       // HEADS * FEAT
#define NEG_SLOPE 0.2f

// ---------------- scratch (static device globals; no allocations) ----------
__device__ __half   g_xh[(size_t)N_NODES * FEAT];    // x in half, 20.5 MB
__device__ __half   g_WT[2][(size_t)HC * FEAT];      // W^T in half, 2x2 MB
__device__ __half   g_xl[(size_t)N_NODES * HC];      // 82 MB
__device__ __half   g_xr[(size_t)N_NODES * HC];      // 82 MB
__device__ int      g_cnt[N_NODES];
__device__ int      g_off[N_NODES + 1];
__device__ int      g_cur[N_NODES];
__device__ int      g_adj[E_TOT];
__device__ float    g_bWc[2];                        // bias @ W_cls + b_cls
__device__ float    g_Wz[FEAT * 8];                  // W_l(head)@W_cls, 16 KB
__device__ float2   g_y[(size_t)N_NODES * HEADS];    // xl_head @ W_cls, 640 KB
__device__ float    g_w[(size_t)HEADS * E_TOT];      // softmax numerators, 2.9 MB

// ---------------- helpers --------------------------------------------------
__device__ __forceinline__ uint32_t smem_u32(const void* p) {
    uint32_t a;
    asm("{ .reg .u64 t; cvta.to.shared.u64 t, %1; cvt.u32.u64 %0, t; }" : "=r"(a) : "l"(p));
    return a;
}
__device__ __forceinline__ void cp_async16(uint32_t dst, const void* src, int bytes) {
    asm volatile("cp.async.ca.shared.global [%0], [%1], 16, %2;"
                 :: "r"(dst), "l"(src), "r"(bytes) : "memory");
}
#define CP_COMMIT() asm volatile("cp.async.commit_group;" ::: "memory")
#define CP_WAIT1()  asm volatile("cp.async.wait_group 1;" ::: "memory")
#define CP_WAIT0()  asm volatile("cp.async.wait_group 0;" ::: "memory")
#define CP_WAIT5()  asm volatile("cp.async.wait_group 5;" ::: "memory")

__device__ __forceinline__ void mma_f16(float* c, const unsigned* a, const unsigned* b) {
    asm volatile(
        "mma.sync.aligned.m16n8k16.row.col.f32.f16.f16.f32 "
        "{%0,%1,%2,%3}, {%4,%5,%6,%7}, {%8,%9}, {%0,%1,%2,%3};\n"
        : "+f"(c[0]), "+f"(c[1]), "+f"(c[2]), "+f"(c[3])
        : "r"(a[0]), "r"(a[1]), "r"(a[2]), "r"(a[3]), "r"(b[0]), "r"(b[1]));
}
__device__ __forceinline__ void ldsm_x4(unsigned& r0, unsigned& r1,
                                        unsigned& r2, unsigned& r3, uint32_t a) {
    asm volatile("ldmatrix.sync.aligned.m8n8.x4.shared.b16 {%0,%1,%2,%3}, [%4];"
                 : "=r"(r0), "=r"(r1), "=r"(r2), "=r"(r3) : "r"(a));
}
__device__ __forceinline__ uint4 lds128(uint32_t a) {
    uint4 v;
    asm volatile("ld.shared.v4.u32 {%0,%1,%2,%3}, [%4];"
                 : "=r"(v.x), "=r"(v.y), "=r"(v.z), "=r"(v.w) : "r"(a));
    return v;
}

// ---------------- x -> half ------------------------------------------------
__global__ void xcvt_kernel(const float* __restrict__ x) {
    int i = blockIdx.x * blockDim.x + threadIdx.x;   // one per 8 floats
    if (i >= N_NODES * FEAT / 8) return;
    float4 a = ((const float4*)x)[2 * i];
    float4 b = ((const float4*)x)[2 * i + 1];
    union { __half2 h[4]; uint4 u; } pk;
    pk.h[0] = __floats2half2_rn(a.x, a.y);
    pk.h[1] = __floats2half2_rn(a.z, a.w);
    pk.h[2] = __floats2half2_rn(b.x, b.y);
    pk.h[3] = __floats2half2_rn(b.z, b.w);
    ((uint4*)g_xh)[i] = pk.u;
}

// ---------------- W [512,2048] -> W^T [2048,512] half ----------------------
__global__ void wtrans_kernel(const float* __restrict__ Wl,
                              const float* __restrict__ Wr) {
    __shared__ float t[32][33];
    const float* W = blockIdx.z ? Wr : Wl;
    __half* WT = g_WT[blockIdx.z];
    int n0 = blockIdx.x * 32, k0 = blockIdx.y * 32;
    int tx = threadIdx.x, ty = threadIdx.y;   // (32,8)
#pragma unroll
    for (int j = 0; j < 4; j++)
        t[ty + j * 8][tx] = W[(size_t)(k0 + ty + j * 8) * HC + n0 + tx];
    __syncthreads();
#pragma unroll
    for (int j = 0; j < 4; j++)
        WT[(size_t)(n0 + ty + j * 8) * FEAT + k0 + tx] = __float2half_rn(t[tx][ty + j * 8]);
}

// ---------------- fp16 mma.sync GEMM (round-4 config, frozen) --------------
#define ROWB 80

__global__ __launch_bounds__(256, 2)
void gemm_f16_kernel() {
    __shared__ __align__(16) char smA[2][128 * ROWB];
    __shared__ __align__(16) char smB[2][128 * ROWB];

    const int z  = blockIdx.z;
    const __half* __restrict__ BT = g_WT[z];
    __half* __restrict__ C = z ? g_xr : g_xl;

    const int bm = blockIdx.y * 128;
    const int bn = blockIdx.x * 128;

    const int tid  = threadIdx.x;
    const int lane = tid & 31;
    const int warp = tid >> 5;
    const int wm = (warp & 1) * 64;
    const int wn = (warp >> 1) * 32;

    const int lr = tid >> 1;
    const int lc = (tid & 1) * 2;

    const uint32_t sA[2] = { smem_u32(smA[0]), smem_u32(smA[1]) };
    const uint32_t sB[2] = { smem_u32(smB[0]), smem_u32(smB[1]) };
    const __half* aRow = g_xh + (size_t)(bm + lr) * FEAT;
    const int aOK = (bm + lr < N_NODES) ? 16 : 0;
    const __half* bRow = BT + (size_t)(bn + lr) * FEAT;

    const int lrow = lane & 15;
    const int lcol = (lane >> 4) * 16;

    float acc[4][4][4];
#pragma unroll
    for (int i = 0; i < 4; i++)
#pragma unroll
        for (int j = 0; j < 4; j++)
#pragma unroll
            for (int r = 0; r < 4; r++) acc[i][j][r] = 0.0f;

#define PREFETCH(chunk, buf) do {                                           \
    int _k0 = (chunk) * 32;                                                 \
    _Pragma("unroll")                                                       \
    for (int j = 0; j < 2; j++) {                                           \
        int c16 = lc + j;                                                   \
        cp_async16(sA[buf] + lr * ROWB + c16 * 16, aRow + _k0 + c16 * 8, aOK); \
        cp_async16(sB[buf] + lr * ROWB + c16 * 16, bRow + _k0 + c16 * 8, 16); \
    }                                                                       \
} while (0)

    PREFETCH(0, 0);
    CP_COMMIT();

    for (int chunk = 0; chunk < 16; chunk++) {
        const int buf = chunk & 1;
        if (chunk < 15) {
            PREFETCH(chunk + 1, buf ^ 1);
            CP_COMMIT();
            CP_WAIT1();
        } else {
            CP_WAIT0();
        }
        __syncthreads();

        const uint32_t aBase = sA[buf] + lrow * ROWB + lcol;
        const uint32_t bBase = sB[buf] + lrow * ROWB + lcol;
#pragma unroll
        for (int ks = 0; ks < 2; ks++) {
            const int kb = ks * 32;
            unsigned a[4][4], bq[2][4];
#pragma unroll
            for (int mt = 0; mt < 4; mt++)
                ldsm_x4(a[mt][0], a[mt][1], a[mt][2], a[mt][3],
                        aBase + (wm + mt * 16) * ROWB + kb);
#pragma unroll
            for (int np = 0; np < 2; np++)
                ldsm_x4(bq[np][0], bq[np][1], bq[np][2], bq[np][3],
                        bBase + (wn + np * 16) * ROWB + kb);
#pragma unroll
            for (int mt = 0; mt < 4; mt++)
#pragma unroll
                for (int nt = 0; nt < 4; nt++) {
                    unsigned bfr[2] = { bq[nt >> 1][(nt & 1)],
                                        bq[nt >> 1][(nt & 1) + 2] };
                    mma_f16(acc[mt][nt], a[mt], bfr);
                }
        }
        __syncthreads();
    }

#pragma unroll
    for (int mt = 0; mt < 4; mt++) {
        int r0 = bm + wm + mt * 16 + (lane >> 2);
#pragma unroll
        for (int nt = 0; nt < 4; nt++) {
            int col = bn + wn + nt * 8 + (lane & 3) * 2;
            if (r0 < N_NODES)
                *(__half2*)(C + (size_t)r0 * HC + col) =
                    __floats2half2_rn(acc[mt][nt][0], acc[mt][nt][1]);
            if (r0 + 8 < N_NODES)
                *(__half2*)(C + (size_t)(r0 + 8) * HC + col) =
                    __floats2half2_rn(acc[mt][nt][2], acc[mt][nt][3]);
        }
    }
}

// ---------------- prep: zero cnt, zero out, Wz, bWc (merged) ---------------
__global__ void prep_kernel(const float* __restrict__ bias,
                            const float* __restrict__ Wl,
                            const float* __restrict__ Wc,
                            const float* __restrict__ bc,
                            float* __restrict__ out) {
    int i = blockIdx.x * blockDim.x + threadIdx.x;
    if (i < N_NODES) g_cnt[i] = 0;
    if (i < N_NODES * 2) out[i] = 0.f;
    if (i < FEAT * 8) {
        int k = i >> 3, hj = i & 7, h = hj >> 1, j = hj & 1;
        const float* wrow = Wl + (size_t)k * HC + h * FEAT;
        float s = 0.f;
        for (int c = 0; c < FEAT; c++)
            s = fmaf(wrow[c], Wc[c * 2 + j], s);
        g_Wz[k * 8 + hj] = s;
    }
    if (blockIdx.x == 0 && threadIdx.x < 64) {
        int w = threadIdx.x >> 5, lane = threadIdx.x & 31;
        float s = 0.f;
        for (int c = lane; c < FEAT; c += 32) s += bias[c] * Wc[c * 2 + w];
#pragma unroll
        for (int off = 16; off; off >>= 1) s += __shfl_xor_sync(0xFFFFFFFFu, s, off);
        if (lane == 0) g_bWc[w] = s + bc[w];
    }
}

// ---------------- CSR build: count -> scan -> scatter ----------------------
__global__ void count_kernel(const int* __restrict__ ei) {
    int e = blockIdx.x * blockDim.x + threadIdx.x;
    if (e >= E_TOT) return;
    int dst = (e < N_EDGES) ? ei[N_EDGES + e] : (e - N_EDGES);
    atomicAdd(&g_cnt[dst], 1);
}
__global__ void scan_kernel() {          // 1 block, 1024 threads
    __shared__ int ssum[1024];
    int t = threadIdx.x;
    int base = t * 20;
    int loc[20];
    int run = 0;
#pragma unroll
    for (int i = 0; i < 20; i++) {
        int idx = base + i;
        int v = (idx < N_NODES) ? g_cnt[idx] : 0;
        loc[i] = run;
        run += v;
    }
    ssum[t] = run;
    __syncthreads();
    for (int d = 1; d < 1024; d <<= 1) {
        int v = (t >= d) ? ssum[t - d] : 0;
        __syncthreads();
        ssum[t] += v;
        __syncthreads();
    }
    int excl = (t == 0) ? 0 : ssum[t - 1];
#pragma unroll
    for (int i = 0; i < 20; i++) {
        int idx = base + i;
        if (idx < N_NODES) {
            g_off[idx] = excl + loc[i];
            g_cur[idx] = excl + loc[i];
        }
    }
    if (t == 1023) g_off[N_NODES] = ssum[1023];
}
__global__ void scatter_kernel(const int* __restrict__ ei) {
    int e = blockIdx.x * blockDim.x + threadIdx.x;
    if (e >= E_TOT) return;
    int src, dst;
    if (e < N_EDGES) { src = ei[e]; dst = ei[N_EDGES + e]; }
    else             { src = dst = e - N_EDGES; }
    int pos = atomicAdd(&g_cur[dst], 1);
    g_adj[pos] = src;
}

// ---------------- y[n][h] = x[n] @ Wz[:,h,:]  (warp per node) --------------
__global__ __launch_bounds__(256)
void y2_kernel() {
    int n    = (blockIdx.x * blockDim.x + threadIdx.x) >> 5;
    int lane = threadIdx.x & 31;
    if (n >= N_NODES) return;

    const uint4* xp = (const uint4*)(g_xh + (size_t)n * FEAT + lane * 16);
    uint4 u0 = xp[0], u1 = xp[1];

    float acc[8];
#pragma unroll
    for (int q = 0; q < 8; q++) acc[q] = 0.f;

#pragma unroll
    for (int j = 0; j < 16; j++) {
        float xk = __half2float(((const __half*)(j < 8 ? (void*)&u0 : (void*)&u1))[j & 7]);
        const float4* wz = (const float4*)(g_Wz + (lane * 16 + j) * 8);
        float4 w0 = __ldg(wz);
        float4 w1 = __ldg(wz + 1);
        acc[0] = fmaf(xk, w0.x, acc[0]); acc[1] = fmaf(xk, w0.y, acc[1]);
        acc[2] = fmaf(xk, w0.z, acc[2]); acc[3] = fmaf(xk, w0.w, acc[3]);
        acc[4] = fmaf(xk, w1.x, acc[4]); acc[5] = fmaf(xk, w1.y, acc[5]);
        acc[6] = fmaf(xk, w1.z, acc[6]); acc[7] = fmaf(xk, w1.w, acc[7]);
    }
#pragma unroll
    for (int off = 16; off; off >>= 1)
#pragma unroll
        for (int q = 0; q < 8; q++)
            acc[q] += __shfl_xor_sync(0xFFFFFFFFu, acc[q], off);
    if (lane == 0) {
#pragma unroll
        for (int h = 0; h < 4; h++)
            g_y[n * 4 + h] = make_float2(acc[2 * h], acc[2 * h + 1]);
    }
}

// ---------------- fused GAT scores + combine: warp per (dst, head) ---------
// cp.async 6-stage per-warp smem pipeline (5-edge lookahead), 256-thr blocks.
// Occupancy preserved (4 blocks/SM by both smem 48KB and regs).
#define SDEPTH 6

__global__ __launch_bounds__(256)
void gat_score_kernel(const float* __restrict__ att,
                      float* __restrict__ out) {
    __shared__ __align__(16) char sbuf[8][SDEPTH][1024];   // 48 KB

    int gw   = (blockIdx.x * blockDim.x + threadIdx.x) >> 5;
    int wid  = (threadIdx.x >> 5);
    int lane = threadIdx.x & 31;
    if (gw >= N_NODES * HEADS) return;
    const int dst = gw >> 2;
    const int h   = gw & 3;

    const int beg = g_off[dst];
    const int nE  = g_off[dst + 1] - beg;
    const uint32_t swb = smem_u32(&sbuf[wid][0][0]);
    const size_t hoff = (size_t)h * 1024;

    // att slice (fp32): j<8 -> att[h*512+lane*8+j]; j>=8 -> +256
    float t[16];
    {
        const float4* a0 = (const float4*)(att + h * FEAT + lane * 8);
        const float4* a1 = (const float4*)(att + h * FEAT + 256 + lane * 8);
        float4 v;
        v = a0[0]; t[0] = v.x; t[1] = v.y; t[2] = v.z; t[3] = v.w;
        v = a0[1]; t[4] = v.x; t[5] = v.y; t[6] = v.z; t[7] = v.w;
        v = a1[0]; t[8] = v.x; t[9] = v.y; t[10] = v.z; t[11] = v.w;
        v = a1[1]; t[12] = v.x; t[13] = v.y; t[14] = v.z; t[15] = v.w;
    }
    // xr slice kept as packed half2
    uint4 xr0, xr1;
    {
        const char* p = (const char*)(g_xr + (size_t)dst * HC) + hoff;
        xr0 = *(const uint4*)(p + lane * 16);
        xr1 = *(const uint4*)(p + 512 + lane * 16);
    }
    const __half2 slope = __floats2half2_rn(NEG_SLOPE, NEG_SLOPE);

    float* __restrict__ wrow = g_w + (size_t)h * E_TOT;

    // issue prefetch of edge k into explicit stage S (1KB slab, coalesced)
#define ISSUE(K, S) do {                                                      \
    const char* _p = (const char*)(g_xl + (size_t)g_adj[beg + (K)] * HC)      \
                     + hoff + lane * 32;                                      \
    uint32_t _d = swb + (S) * 1024 + lane * 32;                               \
    cp_async16(_d, _p, 16);                                                   \
    cp_async16(_d + 16, _p + 16, 16);                                         \
} while (0)

    // prologue: SDEPTH-1 groups
#pragma unroll
    for (int k = 0; k < SDEPTH - 1; k++) {
        if (k < nE) ISSUE(k, k);
        CP_COMMIT();
    }

    int istg = SDEPTH - 1;   // stage for next issued edge
    int cstg = 0;            // stage for next consumed edge
    float d = 0.f;
    for (int i = 0; i < nE; i++) {
        int nxt = i + SDEPTH - 1;
        if (nxt < nE) ISSUE(nxt, istg);
        CP_COMMIT();
        if (++istg == SDEPTH) istg = 0;
        CP_WAIT5();                 // group i complete
        __syncwarp();

        uint32_t s = swb + cstg * 1024;
        if (++cstg == SDEPTH) cstg = 0;
        uint4 a0 = lds128(s + lane * 16);          // conflict-free
        uint4 a1 = lds128(s + 512 + lane * 16);
        const __half2* q0 = (const __half2*)&a0;
        const __half2* q1 = (const __half2*)&a1;
        const __half2* r0 = (const __half2*)&xr0;
        const __half2* r1 = (const __half2*)&xr1;

        float e = 0.f;
#pragma unroll
        for (int j = 0; j < 4; j++) {
            __half2 u0 = __hadd2(q0[j], r0[j]);
            __half2 u1 = __hadd2(q1[j], r1[j]);
            u0 = __hmax2(u0, __hmul2(u0, slope));   // leaky relu in half2
            u1 = __hmax2(u1, __hmul2(u1, slope));
            float2 f0 = __half22float2(u0);
            float2 f1 = __half22float2(u1);
            e = fmaf(f0.x, t[2 * j], e);
            e = fmaf(f0.y, t[2 * j + 1], e);
            e = fmaf(f1.x, t[8 + 2 * j], e);
            e = fmaf(f1.y, t[8 + 2 * j + 1], e);
        }
#pragma unroll
        for (int off = 16; off; off >>= 1)
            e += __shfl_xor_sync(0xFFFFFFFFu, e, off);

        float w = __expf(e);
        d += w;
        if (lane == 0) wrow[beg + i] = w;
    }

    // pass B: lane-parallel weighted combine of y
    float sy0 = 0.f, sy1 = 0.f;
    for (int idx = lane; idx < nE; idx += 32) {
        float w = wrow[beg + idx];
        float2 y = g_y[g_adj[beg + idx] * 4 + h];
        sy0 = fmaf(w, y.x, sy0);
        sy1 = fmaf(w, y.y, sy1);
    }
#pragma unroll
    for (int off = 16; off; off >>= 1) {
        sy0 += __shfl_xor_sync(0xFFFFFFFFu, sy0, off);
        sy1 += __shfl_xor_sync(0xFFFFFFFFu, sy1, off);
    }
    if (lane == 0) {
        float inv = 0.25f / d;
        float a0 = sy0 * inv, a1 = sy1 * inv;
        if (h == 0) { a0 += g_bWc[0]; a1 += g_bWc[1]; }   // out was zero-filled
        atomicAdd(&out[dst * 2 + 0], a0);
        atomicAdd(&out[dst * 2 + 1], a1);
    }
}

// ---------------- launch ---------------------------------------------------
extern "C" void kernel_launch(void* const* d_in, const int* in_sizes, int n_in,
                              void* d_out, int out_size) {
    const float* x    = (const float*)d_in[0];
    const int*   ei   = (const int*)  d_in[1];
    const float* Wl   = (const float*)d_in[2];
    const float* Wr   = (const float*)d_in[3];
    const float* att  = (const float*)d_in[4];
    const float* bias = (const float*)d_in[5];
    const float* Wc   = (const float*)d_in[6];
    const float* bc   = (const float*)d_in[7];
    float* out = (float*)d_out;

    // merged prep (zero cnt/out, Wz, bWc) + CSR build
    prep_kernel<<<(N_NODES * 2 + 255) / 256, 256>>>(bias, Wl, Wc, bc, out);
    count_kernel<<<(E_TOT + 255) / 256, 256>>>(ei);
    scan_kernel<<<1, 1024>>>();
    scatter_kernel<<<(E_TOT + 255) / 256, 256>>>(ei);

    // projections
    xcvt_kernel<<<(N_NODES * FEAT / 8 + 255) / 256, 256>>>(x);
    y2_kernel<<<(N_NODES * 32 + 255) / 256, 256>>>();     // y from x@Wz
    wtrans_kernel<<<dim3(HC / 32, FEAT / 32, 2), dim3(32, 8)>>>(Wl, Wr);
    dim3 ggrid(HC / 128, (N_NODES + 127) / 128, 2);   // (16, 157, 2)
    gemm_f16_kernel<<<ggrid, 256>>>();

    // fused scores + softmax + 2-dim combine (warp per dst,head)
    gat_score_kernel<<<(N_NODES * HEADS * 32 + 255) / 256, 256>>>(att, out);
}

// round 16
// speedup vs baseline: 1.0445x; 1.0445x over previous
#include <cuda_runtime.h>
#include <cuda_fp16.h>
#include <cstdint>

#define N_NODES 20000
#define N_EDGES 160000
#define E_TOT   180000     // edges + self loops
#define FEAT    512
#define HEADS   4
#define HC      2048       // HEADS * FEAT
#define NEG_SLOPE 0.2f

// ---------------- scratch (static device globals; no allocations) ----------
__device__ __half   g_xh[(size_t)N_NODES * FEAT];    // x in half, 20.5 MB
__device__ __half   g_WT[2][(size_t)HC * FEAT];      // W^T in half, 2x2 MB
__device__ __half   g_xl[(size_t)N_NODES * HC];      // 82 MB
__device__ __half   g_xr[(size_t)N_NODES * HC];      // 82 MB
__device__ int      g_cnt[N_NODES];
__device__ int      g_off[N_NODES + 1];
__device__ int      g_cur[N_NODES];
__device__ int      g_adj[E_TOT];
__device__ float    g_bWc[2];                        // bias @ W_cls + b_cls
__device__ float    g_Wz[FEAT * 8];                  // W_l(head)@W_cls, 16 KB
__device__ float2   g_y[(size_t)N_NODES * HEADS];    // xl_head @ W_cls, 640 KB
__device__ float    g_w[(size_t)HEADS * E_TOT];      // softmax numerators, 2.9 MB

// ---------------- helpers --------------------------------------------------
__device__ __forceinline__ uint32_t smem_u32(const void* p) {
    uint32_t a;
    asm("{ .reg .u64 t; cvta.to.shared.u64 t, %1; cvt.u32.u64 %0, t; }" : "=r"(a) : "l"(p));
    return a;
}
__device__ __forceinline__ void cp_async16(uint32_t dst, const void* src, int bytes) {
    asm volatile("cp.async.ca.shared.global [%0], [%1], 16, %2;"
                 :: "r"(dst), "l"(src), "r"(bytes) : "memory");
}
#define CP_COMMIT() asm volatile("cp.async.commit_group;" ::: "memory")
#define CP_WAIT1()  asm volatile("cp.async.wait_group 1;" ::: "memory")
#define CP_WAIT0()  asm volatile("cp.async.wait_group 0;" ::: "memory")
#define CP_WAIT3()  asm volatile("cp.async.wait_group 3;" ::: "memory")

__device__ __forceinline__ void mma_f16(float* c, const unsigned* a, const unsigned* b) {
    asm volatile(
        "mma.sync.aligned.m16n8k16.row.col.f32.f16.f16.f32 "
        "{%0,%1,%2,%3}, {%4,%5,%6,%7}, {%8,%9}, {%0,%1,%2,%3};\n"
        : "+f"(c[0]), "+f"(c[1]), "+f"(c[2]), "+f"(c[3])
        : "r"(a[0]), "r"(a[1]), "r"(a[2]), "r"(a[3]), "r"(b[0]), "r"(b[1]));
}
__device__ __forceinline__ void ldsm_x4(unsigned& r0, unsigned& r1,
                                        unsigned& r2, unsigned& r3, uint32_t a) {
    asm volatile("ldmatrix.sync.aligned.m8n8.x4.shared.b16 {%0,%1,%2,%3}, [%4];"
                 : "=r"(r0), "=r"(r1), "=r"(r2), "=r"(r3) : "r"(a));
}
__device__ __forceinline__ uint4 lds128(uint32_t a) {
    uint4 v;
    asm volatile("ld.shared.v4.u32 {%0,%1,%2,%3}, [%4];"
                 : "=r"(v.x), "=r"(v.y), "=r"(v.z), "=r"(v.w) : "r"(a));
    return v;
}

// ---------------- x -> half ------------------------------------------------
__global__ void xcvt_kernel(const float* __restrict__ x) {
    int i = blockIdx.x * blockDim.x + threadIdx.x;   // one per 8 floats
    if (i >= N_NODES * FEAT / 8) return;
    float4 a = ((const float4*)x)[2 * i];
    float4 b = ((const float4*)x)[2 * i + 1];
    union { __half2 h[4]; uint4 u; } pk;
    pk.h[0] = __floats2half2_rn(a.x, a.y);
    pk.h[1] = __floats2half2_rn(a.z, a.w);
    pk.h[2] = __floats2half2_rn(b.x, b.y);
    pk.h[3] = __floats2half2_rn(b.z, b.w);
    ((uint4*)g_xh)[i] = pk.u;
}

// ---------------- W [512,2048] -> W^T [2048,512] half ----------------------
__global__ void wtrans_kernel(const float* __restrict__ Wl,
                              const float* __restrict__ Wr) {
    __shared__ float t[32][33];
    const float* W = blockIdx.z ? Wr : Wl;
    __half* WT = g_WT[blockIdx.z];
    int n0 = blockIdx.x * 32, k0 = blockIdx.y * 32;
    int tx = threadIdx.x, ty = threadIdx.y;   // (32,8)
#pragma unroll
    for (int j = 0; j < 4; j++)
        t[ty + j * 8][tx] = W[(size_t)(k0 + ty + j * 8) * HC + n0 + tx];
    __syncthreads();
#pragma unroll
    for (int j = 0; j < 4; j++)
        WT[(size_t)(n0 + ty + j * 8) * FEAT + k0 + tx] = __float2half_rn(t[tx][ty + j * 8]);
}

// ---------------- fp16 mma.sync GEMM: R4 tiles, 3-stage cp.async -----------
// BM=BN=128, BK=32. 256 thr, 8 warps (2x4), warp tile 64x32.
// 3 stages x 20480B = 61440B dynamic smem; 2 CTAs/SM preserved.
#define ROWB     80
#define G_ASTG   (128 * ROWB)          // 10240
#define G_STG    (2 * G_ASTG)          // 20480 (A + B)
#define GEMM_SMEM (3 * G_STG)          // 61440

__global__ __launch_bounds__(256, 2)
void gemm_f16_kernel() {
    extern __shared__ __align__(16) char sm[];

    const int z  = blockIdx.z;
    const __half* __restrict__ BT = g_WT[z];
    __half* __restrict__ C = z ? g_xr : g_xl;

    const int bm = blockIdx.y * 128;
    const int bn = blockIdx.x * 128;

    const int tid  = threadIdx.x;
    const int lane = tid & 31;
    const int warp = tid >> 5;
    const int wm = (warp & 1) * 64;
    const int wn = (warp >> 1) * 32;

    const int lr = tid >> 1;
    const int lc = (tid & 1) * 2;

    const uint32_t sbase = smem_u32(sm);
    const __half* aRow = g_xh + (size_t)(bm + lr) * FEAT;
    const int aOK = (bm + lr < N_NODES) ? 16 : 0;
    const __half* bRow = BT + (size_t)(bn + lr) * FEAT;

    const int lrow = lane & 15;
    const int lcol = (lane >> 4) * 16;

    float acc[4][4][4];
#pragma unroll
    for (int i = 0; i < 4; i++)
#pragma unroll
        for (int j = 0; j < 4; j++)
#pragma unroll
            for (int r = 0; r < 4; r++) acc[i][j][r] = 0.0f;

#define PREFETCH(chunk, stg) do {                                             \
    int _k0 = (chunk) * 32;                                                   \
    uint32_t _aS = sbase + (stg) * G_STG;                                     \
    uint32_t _bS = _aS + G_ASTG;                                              \
    _Pragma("unroll")                                                         \
    for (int j = 0; j < 2; j++) {                                             \
        int c16 = lc + j;                                                     \
        cp_async16(_aS + lr * ROWB + c16 * 16, aRow + _k0 + c16 * 8, aOK);    \
        cp_async16(_bS + lr * ROWB + c16 * 16, bRow + _k0 + c16 * 8, 16);     \
    }                                                                         \
} while (0)

    PREFETCH(0, 0); CP_COMMIT();
    PREFETCH(1, 1); CP_COMMIT();

    for (int chunk = 0; chunk < 16; chunk++) {
        if (chunk < 15) CP_WAIT1(); else CP_WAIT0();   // chunk ready
        __syncthreads();

        if (chunk + 2 < 16) {
            PREFETCH(chunk + 2, (chunk + 2) % 3);      // freed stage
            CP_COMMIT();
        }

        const int stg = chunk % 3;
        const uint32_t aBase = sbase + stg * G_STG + lrow * ROWB + lcol;
        const uint32_t bBase = aBase + G_ASTG;
#pragma unroll
        for (int ks = 0; ks < 2; ks++) {
            const int kb = ks * 32;
            unsigned a[4][4], bq[2][4];
#pragma unroll
            for (int mt = 0; mt < 4; mt++)
                ldsm_x4(a[mt][0], a[mt][1], a[mt][2], a[mt][3],
                        aBase + (wm + mt * 16) * ROWB + kb);
#pragma unroll
            for (int np = 0; np < 2; np++)
                ldsm_x4(bq[np][0], bq[np][1], bq[np][2], bq[np][3],
                        bBase + (wn + np * 16) * ROWB + kb);
#pragma unroll
            for (int mt = 0; mt < 4; mt++)
#pragma unroll
                for (int nt = 0; nt < 4; nt++) {
                    unsigned bfr[2] = { bq[nt >> 1][(nt & 1)],
                                        bq[nt >> 1][(nt & 1) + 2] };
                    mma_f16(acc[mt][nt], a[mt], bfr);
                }
        }
    }

#pragma unroll
    for (int mt = 0; mt < 4; mt++) {
        int r0 = bm + wm + mt * 16 + (lane >> 2);
#pragma unroll
        for (int nt = 0; nt < 4; nt++) {
            int col = bn + wn + nt * 8 + (lane & 3) * 2;
            if (r0 < N_NODES)
                *(__half2*)(C + (size_t)r0 * HC + col) =
                    __floats2half2_rn(acc[mt][nt][0], acc[mt][nt][1]);
            if (r0 + 8 < N_NODES)
                *(__half2*)(C + (size_t)(r0 + 8) * HC + col) =
                    __floats2half2_rn(acc[mt][nt][2], acc[mt][nt][3]);
        }
    }
}

// ---------------- CSR build: count -> scan -> scatter ----------------------
__global__ void zero_cnt_kernel() {
    int i = blockIdx.x * blockDim.x + threadIdx.x;
    if (i < N_NODES) g_cnt[i] = 0;
}
__global__ void count_kernel(const int* __restrict__ ei) {
    int e = blockIdx.x * blockDim.x + threadIdx.x;
    if (e >= E_TOT) return;
    int dst = (e < N_EDGES) ? ei[N_EDGES + e] : (e - N_EDGES);
    atomicAdd(&g_cnt[dst], 1);
}
__global__ void scan_kernel() {          // 1 block, 1024 threads
    __shared__ int ssum[1024];
    int t = threadIdx.x;
    int base = t * 20;
    int loc[20];
    int run = 0;
#pragma unroll
    for (int i = 0; i < 20; i++) {
        int idx = base + i;
        int v = (idx < N_NODES) ? g_cnt[idx] : 0;
        loc[i] = run;
        run += v;
    }
    ssum[t] = run;
    __syncthreads();
    for (int d = 1; d < 1024; d <<= 1) {
        int v = (t >= d) ? ssum[t - d] : 0;
        __syncthreads();
        ssum[t] += v;
        __syncthreads();
    }
    int excl = (t == 0) ? 0 : ssum[t - 1];
#pragma unroll
    for (int i = 0; i < 20; i++) {
        int idx = base + i;
        if (idx < N_NODES) {
            g_off[idx] = excl + loc[i];
            g_cur[idx] = excl + loc[i];
        }
    }
    if (t == 1023) g_off[N_NODES] = ssum[1023];
}
__global__ void scatter_kernel(const int* __restrict__ ei) {
    int e = blockIdx.x * blockDim.x + threadIdx.x;
    if (e >= E_TOT) return;
    int src, dst;
    if (e < N_EDGES) { src = ei[e]; dst = ei[N_EDGES + e]; }
    else             { src = dst = e - N_EDGES; }
    int pos = atomicAdd(&g_cur[dst], 1);
    g_adj[pos] = src;
}

// ---------------- output init: out[n] = bias @ W_cls + b_cls ---------------
__global__ void bwc_kernel(const float* __restrict__ bias,
                           const float* __restrict__ Wc,
                           const float* __restrict__ bc) {
    int w = threadIdx.x >> 5, lane = threadIdx.x & 31;   // 2 warps
    float s = 0.f;
    for (int c = lane; c < FEAT; c += 32) s += bias[c] * Wc[c * 2 + w];
#pragma unroll
    for (int off = 16; off; off >>= 1) s += __shfl_xor_sync(0xFFFFFFFFu, s, off);
    if (lane == 0) g_bWc[w] = s + bc[w];
}
__global__ void fill_kernel(float* __restrict__ out) {
    int i = blockIdx.x * blockDim.x + threadIdx.x;
    if (i < N_NODES * 2) out[i] = g_bWc[i & 1];
}

// ---------------- Wz[k][h*2+j] = sum_c W_l[k, h*512+c] * Wc[c, j] ----------
__global__ void wz_kernel(const float* __restrict__ Wl,
                          const float* __restrict__ Wc) {
    int idx = blockIdx.x * blockDim.x + threadIdx.x;   // 0..4095
    if (idx >= FEAT * 8) return;
    int k = idx >> 3, hj = idx & 7, h = hj >> 1, j = hj & 1;
    const float* wrow = Wl + (size_t)k * HC + h * FEAT;
    float s = 0.f;
    for (int c = 0; c < FEAT; c++)
        s = fmaf(wrow[c], Wc[c * 2 + j], s);
    g_Wz[k * 8 + hj] = s;
}

// ---------------- y[n][h] = x[n] @ Wz[:,h,:]  (warp per node) --------------
__global__ __launch_bounds__(256)
void y2_kernel() {
    int n    = (blockIdx.x * blockDim.x + threadIdx.x) >> 5;
    int lane = threadIdx.x & 31;
    if (n >= N_NODES) return;

    const uint4* xp = (const uint4*)(g_xh + (size_t)n * FEAT + lane * 16);
    uint4 u0 = xp[0], u1 = xp[1];

    float acc[8];
#pragma unroll
    for (int q = 0; q < 8; q++) acc[q] = 0.f;

#pragma unroll
    for (int j = 0; j < 16; j++) {
        float xk = __half2float(((const __half*)(j < 8 ? (void*)&u0 : (void*)&u1))[j & 7]);
        const float4* wz = (const float4*)(g_Wz + (lane * 16 + j) * 8);
        float4 w0 = __ldg(wz);
        float4 w1 = __ldg(wz + 1);
        acc[0] = fmaf(xk, w0.x, acc[0]); acc[1] = fmaf(xk, w0.y, acc[1]);
        acc[2] = fmaf(xk, w0.z, acc[2]); acc[3] = fmaf(xk, w0.w, acc[3]);
        acc[4] = fmaf(xk, w1.x, acc[4]); acc[5] = fmaf(xk, w1.y, acc[5]);
        acc[6] = fmaf(xk, w1.z, acc[6]); acc[7] = fmaf(xk, w1.w, acc[7]);
    }
#pragma unroll
    for (int off = 16; off; off >>= 1)
#pragma unroll
        for (int q = 0; q < 8; q++)
            acc[q] += __shfl_xor_sync(0xFFFFFFFFu, acc[q], off);
    if (lane == 0) {
#pragma unroll
        for (int h = 0; h < 4; h++)
            g_y[n * 4 + h] = make_float2(acc[2 * h], acc[2 * h + 1]);
    }
}

// ---------------- fused GAT scores + combine: warp per (dst, head) ---------
// R14 champion config: cp.async 4-stage per-warp smem pipeline, half2 xr.
#define SDEPTH 4

__global__ __launch_bounds__(256)
void gat_score_kernel(const float* __restrict__ att,
                      float* __restrict__ out) {
    __shared__ __align__(16) char sbuf[8][SDEPTH][1024];   // 32 KB

    int gw   = (blockIdx.x * blockDim.x + threadIdx.x) >> 5;
    int wid  = (threadIdx.x >> 5);
    int lane = threadIdx.x & 31;
    if (gw >= N_NODES * HEADS) return;
    const int dst = gw >> 2;
    const int h   = gw & 3;

    const int beg = g_off[dst];
    const int nE  = g_off[dst + 1] - beg;
    const uint32_t swb = smem_u32(&sbuf[wid][0][0]);
    const size_t hoff = (size_t)h * 1024;

    // att slice (fp32): j<8 -> att[h*512+lane*8+j]; j>=8 -> +256
    float t[16];
    {
        const float4* a0 = (const float4*)(att + h * FEAT + lane * 8);
        const float4* a1 = (const float4*)(att + h * FEAT + 256 + lane * 8);
        float4 v;
        v = a0[0]; t[0] = v.x; t[1] = v.y; t[2] = v.z; t[3] = v.w;
        v = a0[1]; t[4] = v.x; t[5] = v.y; t[6] = v.z; t[7] = v.w;
        v = a1[0]; t[8] = v.x; t[9] = v.y; t[10] = v.z; t[11] = v.w;
        v = a1[1]; t[12] = v.x; t[13] = v.y; t[14] = v.z; t[15] = v.w;
    }
    // xr slice kept as packed half2
    uint4 xr0, xr1;
    {
        const char* p = (const char*)(g_xr + (size_t)dst * HC) + hoff;
        xr0 = *(const uint4*)(p + lane * 16);
        xr1 = *(const uint4*)(p + 512 + lane * 16);
    }
    const __half2 slope = __floats2half2_rn(NEG_SLOPE, NEG_SLOPE);

    float* __restrict__ wrow = g_w + (size_t)h * E_TOT;

    // issue prefetch of edge k into stage k%SDEPTH (1KB slab, coalesced)
#define ISSUE(K) do {                                                         \
    const char* _p = (const char*)(g_xl + (size_t)g_adj[beg + (K)] * HC)      \
                     + hoff + lane * 32;                                      \
    uint32_t _d = swb + ((K) & (SDEPTH - 1)) * 1024 + lane * 32;              \
    cp_async16(_d, _p, 16);                                                   \
    cp_async16(_d + 16, _p + 16, 16);                                         \
} while (0)

    // prologue: SDEPTH-1 groups
#pragma unroll
    for (int k = 0; k < SDEPTH - 1; k++) {
        if (k < nE) ISSUE(k);
        CP_COMMIT();
    }

    float d = 0.f;
    for (int i = 0; i < nE; i++) {
        int nxt = i + SDEPTH - 1;
        if (nxt < nE) ISSUE(nxt);
        CP_COMMIT();
        CP_WAIT3();                 // group i complete
        __syncwarp();

        uint32_t s = swb + (i & (SDEPTH - 1)) * 1024;
        uint4 a0 = lds128(s + lane * 16);          // conflict-free
        uint4 a1 = lds128(s + 512 + lane * 16);
        const __half2* q0 = (const __half2*)&a0;
        const __half2* q1 = (const __half2*)&a1;
        const __half2* r0 = (const __half2*)&xr0;
        const __half2* r1 = (const __half2*)&xr1;

        float e = 0.f;
#pragma unroll
        for (int j = 0; j < 4; j++) {
            __half2 u0 = __hadd2(q0[j], r0[j]);
            __half2 u1 = __hadd2(q1[j], r1[j]);
            u0 = __hmax2(u0, __hmul2(u0, slope));   // leaky relu in half2
            u1 = __hmax2(u1, __hmul2(u1, slope));
            float2 f0 = __half22float2(u0);
            float2 f1 = __half22float2(u1);
            e = fmaf(f0.x, t[2 * j], e);
            e = fmaf(f0.y, t[2 * j + 1], e);
            e = fmaf(f1.x, t[8 + 2 * j], e);
            e = fmaf(f1.y, t[8 + 2 * j + 1], e);
        }
#pragma unroll
        for (int off = 16; off; off >>= 1)
            e += __shfl_xor_sync(0xFFFFFFFFu, e, off);

        float w = __expf(e);
        d += w;
        if (lane == 0) wrow[beg + i] = w;
    }

    // pass B: lane-parallel weighted combine of y
    float sy0 = 0.f, sy1 = 0.f;
    for (int idx = lane; idx < nE; idx += 32) {
        float w = wrow[beg + idx];
        float2 y = g_y[g_adj[beg + idx] * 4 + h];
        sy0 = fmaf(w, y.x, sy0);
        sy1 = fmaf(w, y.y, sy1);
    }
#pragma unroll
    for (int off = 16; off; off >>= 1) {
        sy0 += __shfl_xor_sync(0xFFFFFFFFu, sy0, off);
        sy1 += __shfl_xor_sync(0xFFFFFFFFu, sy1, off);
    }
    if (lane == 0) {
        float inv = 0.25f / d;
        atomicAdd(&out[dst * 2 + 0], sy0 * inv);
        atomicAdd(&out[dst * 2 + 1], sy1 * inv);
    }
}

// ---------------- launch ---------------------------------------------------
extern "C" void kernel_launch(void* const* d_in, const int* in_sizes, int n_in,
                              void* d_out, int out_size) {
    const float* x    = (const float*)d_in[0];
    const int*   ei   = (const int*)  d_in[1];
    const float* Wl   = (const float*)d_in[2];
    const float* Wr   = (const float*)d_in[3];
    const float* att  = (const float*)d_in[4];
    const float* bias = (const float*)d_in[5];
    const float* Wc   = (const float*)d_in[6];
    const float* bc   = (const float*)d_in[7];
    float* out = (float*)d_out;

    static bool attr_set = false;
    if (!attr_set) {
        cudaFuncSetAttribute(gemm_f16_kernel,
                             cudaFuncAttributeMaxDynamicSharedMemorySize, GEMM_SMEM);
        attr_set = true;
    }

    // CSR build + output init (independent of GEMM)
    zero_cnt_kernel<<<(N_NODES + 255) / 256, 256>>>();
    count_kernel<<<(E_TOT + 255) / 256, 256>>>(ei);
    scan_kernel<<<1, 1024>>>();
    scatter_kernel<<<(E_TOT + 255) / 256, 256>>>(ei);
    bwc_kernel<<<1, 64>>>(bias, Wc, bc);
    fill_kernel<<<(N_NODES * 2 + 255) / 256, 256>>>(out);
    wz_kernel<<<(FEAT * 8 + 255) / 256, 256>>>(Wl, Wc);

    // projections
    xcvt_kernel<<<(N_NODES * FEAT / 8 + 255) / 256, 256>>>(x);
    y2_kernel<<<(N_NODES * 32 + 255) / 256, 256>>>();     // y from x@Wz
    wtrans_kernel<<<dim3(HC / 32, FEAT / 32, 2), dim3(32, 8)>>>(Wl, Wr);
    dim3 ggrid(HC / 128, (N_NODES + 127) / 128, 2);   // (16, 157, 2)
    gemm_f16_kernel<<<ggrid, 256, GEMM_SMEM>>>();

    // fused scores + softmax + 2-dim combine (warp per dst,head)
    gat_score_kernel<<<(N_NODES * HEADS * 32 + 255) / 256, 256>>>(att, out);
}